// round 2
// baseline (speedup 1.0000x reference)
#include <cuda_runtime.h>

// Problem constants (fixed by dataset): N=100000, E=1600000, DIM=128, HEADS=8, HEAD_DIM=16
#define NMAX 100000
#define EMAX 1600000

// Scratch (allocation-free rule: __device__ globals)
static __device__ float g_xh[NMAX * 128];      // projected features [N,128]
static __device__ float g_asrc[NMAX * 8];      // per-node src logits [N,H]
static __device__ float g_adst[NMAX * 8];      // per-node dst logits [N,H]
static __device__ float g_exself[NMAX * 8];    // exp(leakyrelu) of self loop
static __device__ float g_denom[NMAX * 8];     // softmax denominators
static __device__ float g_ex[(size_t)EMAX * 8];// per-edge exp scores

__device__ __forceinline__ void red_add_v4(float* p, float a, float b, float c, float d) {
    asm volatile("red.global.add.v4.f32 [%0], {%1,%2,%3,%4};"
                 :: "l"(p), "f"(a), "f"(b), "f"(c), "f"(d) : "memory");
}

// ---------------------------------------------------------------------------
// Kernel 1: xh = x @ W^T + b_proj     (x:[n,128], W:[128,128] row-major)
// Block tile: 64 rows x 128 cols, 256 threads, 8x4 register tile per thread.
// W staged k-major in SMEM -> per-k W read is one conflict-free LDS.128;
// x reads are warp-broadcast (all lanes of a warp share ty).
// ---------------------------------------------------------------------------
__global__ __launch_bounds__(256) void gemm_kernel(const float* __restrict__ x,
                                                   const float* __restrict__ W,
                                                   const float* __restrict__ b,
                                                   int n) {
    __shared__ float xs[64][33];     // [row][k], padded
    __shared__ float wt[32 * 132];   // [k][c], pitch 132 floats (16B-aligned rows)

    const int t  = threadIdx.x;
    const int tx = t & 31;           // column group: cols tx*4 .. tx*4+3
    const int ty = t >> 5;           // row group:    rows ty*8 .. ty*8+7
    const int row0 = blockIdx.x * 64;

    float acc[8][4];
#pragma unroll
    for (int i = 0; i < 8; i++)
#pragma unroll
        for (int j = 0; j < 4; j++) acc[i][j] = 0.f;

    for (int kt = 0; kt < 4; kt++) {
        const int k0 = kt * 32;
        // load x tile [64][32], coalesced
#pragma unroll
        for (int i = 0; i < 8; i++) {
            int idx = t + i * 256;
            int r = idx >> 5, k = idx & 31;
            int row = row0 + r;
            xs[r][k] = (row < n) ? x[row * 128 + k0 + k] : 0.f;
        }
        // load W tile transposed: wt[k*132 + c] = W[c*128 + k0 + k], coalesced reads
#pragma unroll
        for (int i = 0; i < 16; i++) {
            int idx = t + i * 256;
            int c = idx >> 5, k = idx & 31;
            wt[k * 132 + c] = W[c * 128 + k0 + k];
        }
        __syncthreads();
#pragma unroll
        for (int k = 0; k < 32; k++) {
            float4 w4 = *reinterpret_cast<const float4*>(&wt[k * 132 + tx * 4]);
#pragma unroll
            for (int i = 0; i < 8; i++) {
                float xv = xs[ty * 8 + i][k];
                acc[i][0] += xv * w4.x;
                acc[i][1] += xv * w4.y;
                acc[i][2] += xv * w4.z;
                acc[i][3] += xv * w4.w;
            }
        }
        __syncthreads();
    }

    float4 bb = *reinterpret_cast<const float4*>(&b[tx * 4]);
#pragma unroll
    for (int i = 0; i < 8; i++) {
        int row = row0 + ty * 8 + i;
        if (row < n) {
            float4 o;
            o.x = acc[i][0] + bb.x;
            o.y = acc[i][1] + bb.y;
            o.z = acc[i][2] + bb.z;
            o.w = acc[i][3] + bb.w;
            *reinterpret_cast<float4*>(&g_xh[row * 128 + tx * 4]) = o;
        }
    }
}

// ---------------------------------------------------------------------------
// Kernel 2: per-(node,head) attention logits a_src / a_dst (dot over 16 dims)
// ---------------------------------------------------------------------------
__global__ __launch_bounds__(256) void att_kernel(const float* __restrict__ att_s,
                                                  const float* __restrict__ att_d,
                                                  int n) {
    int t = blockIdx.x * 256 + threadIdx.x;
    if (t >= n * 8) return;
    int nid = t >> 3, h = t & 7;
    const float4* xr = reinterpret_cast<const float4*>(g_xh + nid * 128 + h * 16);
    const float4* sr = reinterpret_cast<const float4*>(att_s + h * 16);
    const float4* dr = reinterpret_cast<const float4*>(att_d + h * 16);
    float s = 0.f, d = 0.f;
#pragma unroll
    for (int q = 0; q < 4; q++) {
        float4 xv = xr[q], sv = sr[q], dv = dr[q];
        s += xv.x * sv.x + xv.y * sv.y + xv.z * sv.z + xv.w * sv.w;
        d += xv.x * dv.x + xv.y * dv.y + xv.z * dv.z + xv.w * dv.w;
    }
    g_asrc[t] = s;
    g_adst[t] = d;
}

// ---------------------------------------------------------------------------
// Kernel 3: self-loop exp scores initialize the denominators
// (no segment-max needed: exp(a-mx)/sum exp(a-mx) == exp(a)/sum exp(a), and
//  logits have |a| < ~10 so expf cannot overflow)
// ---------------------------------------------------------------------------
__global__ __launch_bounds__(256) void self_init_kernel(int n) {
    int t = blockIdx.x * 256 + threadIdx.x;
    if (t >= n * 8) return;
    float s = g_asrc[t] + g_adst[t];
    s = (s > 0.f) ? s : 0.2f * s;
    float ex = expf(s);
    g_exself[t] = ex;
    g_denom[t]  = ex;
}

// ---------------------------------------------------------------------------
// Kernel 4: per-edge exp scores; accumulate softmax denominators (vector RED)
// ---------------------------------------------------------------------------
__global__ __launch_bounds__(256) void edge_exp_kernel(const int* __restrict__ ei, int E) {
    int e = blockIdx.x * 256 + threadIdx.x;
    if (e >= E) return;
    int src = ei[e];
    int dst = ei[E + e];
    const float4* as = reinterpret_cast<const float4*>(g_asrc + src * 8);
    const float4* ad = reinterpret_cast<const float4*>(g_adst + dst * 8);
    float4 a0 = as[0], a1 = as[1];
    float4 b0 = ad[0], b1 = ad[1];
    float v[8] = {a0.x + b0.x, a0.y + b0.y, a0.z + b0.z, a0.w + b0.w,
                  a1.x + b1.x, a1.y + b1.y, a1.z + b1.z, a1.w + b1.w};
#pragma unroll
    for (int j = 0; j < 8; j++) {
        float s = v[j];
        s = (s > 0.f) ? s : 0.2f * s;
        v[j] = expf(s);
    }
    float4* exp_out = reinterpret_cast<float4*>(g_ex + (size_t)e * 8);
    float4 e0 = {v[0], v[1], v[2], v[3]};
    float4 e1 = {v[4], v[5], v[6], v[7]};
    exp_out[0] = e0;
    exp_out[1] = e1;
    red_add_v4(g_denom + dst * 8,     e0.x, e0.y, e0.z, e0.w);
    red_add_v4(g_denom + dst * 8 + 4, e1.x, e1.y, e1.z, e1.w);
}

// ---------------------------------------------------------------------------
// Kernel 5: initialize output = bias + self-loop message (plain stores; runs
// after denominators are final, before edge scatter begins adding)
// ---------------------------------------------------------------------------
__global__ __launch_bounds__(256) void out_init_kernel(const float* __restrict__ bias,
                                                       float* __restrict__ out, int n) {
    int t = blockIdx.x * 256 + threadIdx.x;
    if (t >= n * 32) return;
    int nid = t >> 5, q = t & 31, h = q >> 2;
    float w = g_exself[nid * 8 + h] / g_denom[nid * 8 + h];
    float4 xv = reinterpret_cast<const float4*>(g_xh)[nid * 32 + q];
    float4 bv = reinterpret_cast<const float4*>(bias)[q];
    float4 o = {bv.x + w * xv.x, bv.y + w * xv.y, bv.z + w * xv.z, bv.w + w * xv.w};
    reinterpret_cast<float4*>(out)[t] = o;
}

// ---------------------------------------------------------------------------
// Kernel 6: edge scatter. One warp per edge; lane l owns 4 output floats
// (head h = l/4). Softmax weight computed by lanes 0..7, broadcast by shfl.
// Vector RED (red.global.add.v4.f32) quarters the atomic instruction count.
// ---------------------------------------------------------------------------
__global__ __launch_bounds__(256) void scatter_kernel(const int* __restrict__ ei,
                                                      float* __restrict__ out, int E) {
    int gt = blockIdx.x * 256 + threadIdx.x;
    int e = gt >> 5;
    int lane = gt & 31;
    if (e >= E) return;
    int src = ei[e];
    int dst = ei[E + e];
    float wv = 0.f;
    if (lane < 8) wv = g_ex[(size_t)e * 8 + lane] / g_denom[dst * 8 + lane];
    float w = __shfl_sync(0xffffffffu, wv, lane >> 2);
    float4 xv = reinterpret_cast<const float4*>(g_xh)[src * 32 + lane];
    red_add_v4(out + dst * 128 + lane * 4, w * xv.x, w * xv.y, w * xv.z, w * xv.w);
}

// ---------------------------------------------------------------------------
extern "C" void kernel_launch(void* const* d_in, const int* in_sizes, int n_in,
                              void* d_out, int out_size) {
    const float* x     = (const float*)d_in[0];
    const int*   ei    = (const int*)  d_in[1];
    const float* W     = (const float*)d_in[2];
    const float* bproj = (const float*)d_in[3];
    const float* att_s = (const float*)d_in[4];
    const float* att_d = (const float*)d_in[5];
    const float* bias  = (const float*)d_in[6];
    float* out = (float*)d_out;

    const int n = in_sizes[0] / 128;
    const int E = in_sizes[1] / 2;

    gemm_kernel<<<(n + 63) / 64, 256>>>(x, W, bproj, n);
    att_kernel<<<(n * 8 + 255) / 256, 256>>>(att_s, att_d, n);
    self_init_kernel<<<(n * 8 + 255) / 256, 256>>>(n);
    edge_exp_kernel<<<(E + 255) / 256, 256>>>(ei, E);
    out_init_kernel<<<(n * 32 + 255) / 256, 256>>>(bias, out, n);
    scatter_kernel<<<(int)(((long long)E * 32 + 255) / 256), 256>>>(ei, out, E);
}

// round 3
// speedup vs baseline: 1.9832x; 1.9832x over previous
#include <cuda_runtime.h>

// Problem constants: N=100000, E=1600000, DIM=128, HEADS=8, HEAD_DIM=16
#define NMAX 100000
#define EMAX 1600000

// Scratch (__device__ globals per allocation-free rule)
static __device__ float g_xh[NMAX * 128];      // projected features [N,128]
static __device__ float g_asrc[NMAX * 8];      // per-node src logits [N,H]
static __device__ float g_adst[NMAX * 8];      // per-node dst logits [N,H]
static __device__ int   g_cnt[NMAX];           // in-degree per node
static __device__ int   g_off[NMAX];           // CSR row offsets (exclusive scan of cnt)
static __device__ int   g_cur[NMAX];           // fill cursors
static __device__ int   g_bsum[128];           // block sums for scan
static __device__ int   g_csrc[EMAX];          // CSR: source node per (dst-sorted) edge

// ---------------------------------------------------------------------------
// f32x2 packed-FMA helpers (sm_10x: fma.rn.f32x2 = 2 FMAs in one fma-pipe op)
// ---------------------------------------------------------------------------
__device__ __forceinline__ void ffma2(unsigned long long& d, unsigned long long a,
                                      unsigned long long b, unsigned long long c) {
    asm("fma.rn.f32x2 %0, %1, %2, %3;" : "=l"(d) : "l"(a), "l"(b), "l"(c));
}
__device__ __forceinline__ unsigned long long dup2(float v) {
    unsigned long long r;
    asm("mov.b64 %0, {%1, %1};" : "=l"(r) : "f"(v));
    return r;
}
__device__ __forceinline__ float2 unpk2(unsigned long long v) {
    float2 f;
    asm("mov.b64 {%0, %1}, %2;" : "=f"(f.x), "=f"(f.y) : "l"(v));
    return f;
}

// ---------------------------------------------------------------------------
// Kernel 1: xh = x @ W^T + b_proj  via packed f32x2 FMAs.
// Block tile 64x128, 256 threads. x tile stored k-major so row-pairs load as
// one ld.shared.v2.f32 (already packed). W tile k-major, LDS.128 per k.
// Per thread: 4 row-pairs x 4 cols accumulators (u64-packed).
// ---------------------------------------------------------------------------
__global__ __launch_bounds__(256) void gemm_kernel(const float* __restrict__ x,
                                                   const float* __restrict__ W,
                                                   const float* __restrict__ b,
                                                   int n) {
    __shared__ float xs[32 * 66];    // [k][row], pitch 66 (8B-aligned row pairs)
    __shared__ float wt[32 * 132];   // [k][c],   pitch 132

    const int t  = threadIdx.x;
    const int tx = t & 31;           // cols tx*4 .. tx*4+3
    const int ty = t >> 5;           // rows ty*8 .. ty*8+7 (4 pairs)
    const int row0 = blockIdx.x * 64;

    unsigned long long acc[4][4];
#pragma unroll
    for (int p = 0; p < 4; p++)
#pragma unroll
        for (int j = 0; j < 4; j++) acc[p][j] = 0ULL;

    for (int kt = 0; kt < 4; kt++) {
        const int k0 = kt * 32;
        // x tile: gmem coalesced along k, stored transposed [k][row]
#pragma unroll
        for (int i = 0; i < 8; i++) {
            int idx = t + i * 256;
            int r = idx >> 5, k = idx & 31;
            int row = row0 + r;
            xs[k * 66 + r] = (row < n) ? x[row * 128 + k0 + k] : 0.f;
        }
        // W tile transposed: wt[k*132 + c] = W[c*128 + k0 + k]
#pragma unroll
        for (int i = 0; i < 16; i++) {
            int idx = t + i * 256;
            int c = idx >> 5, k = idx & 31;
            wt[k * 132 + c] = W[c * 128 + k0 + k];
        }
        __syncthreads();
#pragma unroll
        for (int k = 0; k < 32; k++) {
            float4 w4 = *reinterpret_cast<const float4*>(&wt[k * 132 + tx * 4]);
            unsigned long long wd0 = dup2(w4.x), wd1 = dup2(w4.y);
            unsigned long long wd2 = dup2(w4.z), wd3 = dup2(w4.w);
#pragma unroll
            for (int p = 0; p < 4; p++) {
                unsigned long long xp =
                    *reinterpret_cast<const unsigned long long*>(&xs[k * 66 + ty * 8 + p * 2]);
                ffma2(acc[p][0], xp, wd0, acc[p][0]);
                ffma2(acc[p][1], xp, wd1, acc[p][1]);
                ffma2(acc[p][2], xp, wd2, acc[p][2]);
                ffma2(acc[p][3], xp, wd3, acc[p][3]);
            }
        }
        __syncthreads();
    }

    float4 bb = *reinterpret_cast<const float4*>(&b[tx * 4]);
#pragma unroll
    for (int p = 0; p < 4; p++) {
        float2 a0 = unpk2(acc[p][0]), a1 = unpk2(acc[p][1]);
        float2 a2 = unpk2(acc[p][2]), a3 = unpk2(acc[p][3]);
        int r0 = row0 + ty * 8 + p * 2;
        if (r0 < n) {
            float4 o = {a0.x + bb.x, a1.x + bb.y, a2.x + bb.z, a3.x + bb.w};
            *reinterpret_cast<float4*>(&g_xh[r0 * 128 + tx * 4]) = o;
        }
        if (r0 + 1 < n) {
            float4 o = {a0.y + bb.x, a1.y + bb.y, a2.y + bb.z, a3.y + bb.w};
            *reinterpret_cast<float4*>(&g_xh[(r0 + 1) * 128 + tx * 4]) = o;
        }
    }
}

// ---------------------------------------------------------------------------
// Kernel 2: per-(node,head) attention logits
// ---------------------------------------------------------------------------
__global__ __launch_bounds__(256) void att_kernel(const float* __restrict__ att_s,
                                                  const float* __restrict__ att_d,
                                                  int n) {
    int t = blockIdx.x * 256 + threadIdx.x;
    if (t >= n * 8) return;
    int nid = t >> 3, h = t & 7;
    const float4* xr = reinterpret_cast<const float4*>(g_xh + nid * 128 + h * 16);
    const float4* sr = reinterpret_cast<const float4*>(att_s + h * 16);
    const float4* dr = reinterpret_cast<const float4*>(att_d + h * 16);
    float s = 0.f, d = 0.f;
#pragma unroll
    for (int q = 0; q < 4; q++) {
        float4 xv = xr[q], sv = sr[q], dv = dr[q];
        s += xv.x * sv.x + xv.y * sv.y + xv.z * sv.z + xv.w * sv.w;
        d += xv.x * dv.x + xv.y * dv.y + xv.z * dv.z + xv.w * dv.w;
    }
    g_asrc[t] = s;
    g_adst[t] = d;
}

// ---------------------------------------------------------------------------
// CSR construction: zero -> histogram -> scan(3) -> fill
// ---------------------------------------------------------------------------
__global__ __launch_bounds__(256) void zero_kernel(int n) {
    int t = blockIdx.x * 256 + threadIdx.x;
    if (t < n) g_cnt[t] = 0;
}

__global__ __launch_bounds__(256) void hist_kernel(const int* __restrict__ ei, int E) {
    int e = blockIdx.x * 256 + threadIdx.x;
    if (e < E) atomicAdd(&g_cnt[ei[E + e]], 1);
}

// scan over 1024 elements per block (256 threads x 4 sequential)
__global__ __launch_bounds__(256) void scan1_kernel(int n) {
    __shared__ int s[256];
    int b = blockIdx.x, t = threadIdx.x;
    int base = b * 1024 + t * 4;
    int v[4];
#pragma unroll
    for (int j = 0; j < 4; j++) v[j] = (base + j < n) ? g_cnt[base + j] : 0;
    int local = v[0] + v[1] + v[2] + v[3];
    s[t] = local;
    __syncthreads();
    for (int off = 1; off < 256; off <<= 1) {
        int x = (t >= off) ? s[t - off] : 0;
        __syncthreads();
        s[t] += x;
        __syncthreads();
    }
    int run = s[t] - local;
#pragma unroll
    for (int j = 0; j < 4; j++) {
        if (base + j < n) g_off[base + j] = run;
        run += v[j];
    }
    if (t == 255) g_bsum[b] = s[255];
}

__global__ __launch_bounds__(128) void scan2_kernel(int nb) {
    __shared__ int s[128];
    int t = threadIdx.x;
    int v = (t < nb) ? g_bsum[t] : 0;
    s[t] = v;
    __syncthreads();
    for (int off = 1; off < 128; off <<= 1) {
        int x = (t >= off) ? s[t - off] : 0;
        __syncthreads();
        s[t] += x;
        __syncthreads();
    }
    if (t < nb) g_bsum[t] = s[t] - v;   // exclusive
}

__global__ __launch_bounds__(256) void scan3_kernel(int n) {
    int t = blockIdx.x * 256 + threadIdx.x;
    if (t < n) {
        int o = g_off[t] + g_bsum[t >> 10];
        g_off[t] = o;
        g_cur[t] = o;
    }
}

__global__ __launch_bounds__(256) void fill_kernel(const int* __restrict__ ei, int E) {
    int e = blockIdx.x * 256 + threadIdx.x;
    if (e >= E) return;
    int pos = atomicAdd(&g_cur[ei[E + e]], 1);
    g_csrc[pos] = ei[e];
}

// ---------------------------------------------------------------------------
// Fused gather: one warp per destination node. Single pass computes
//   out = (ex_self*xh[node] + sum ex_e*xh[src]) / (ex_self + sum ex_e) + bias
// lanes 0..7 own head logits/exps; weight broadcast via shfl; lane l owns
// output floats [4l..4l+3] (head l/4). Read-only, no atomics.
// ---------------------------------------------------------------------------
__global__ __launch_bounds__(256) void gather_kernel(const float* __restrict__ bias,
                                                     float* __restrict__ out, int n) {
    int gt = blockIdx.x * 256 + threadIdx.x;
    int node = gt >> 5, lane = gt & 31;
    if (node >= n) return;
    const float4* xh4 = reinterpret_cast<const float4*>(g_xh);

    float ad = 0.f, ex = 0.f, dsum = 0.f;
    if (lane < 8) {
        ad = g_adst[node * 8 + lane];
        float s = g_asrc[node * 8 + lane] + ad;
        s = (s > 0.f) ? s : 0.2f * s;
        ex = __expf(s);
        dsum = ex;
    }
    float w = __shfl_sync(0xffffffffu, ex, lane >> 2);
    float4 xv = xh4[node * 32 + lane];
    float4 acc = {w * xv.x, w * xv.y, w * xv.z, w * xv.w};

    int beg = g_off[node], cnt = g_cnt[node];
    int src = (cnt > 0) ? g_csrc[beg] : 0;
    for (int i = 0; i < cnt; i++) {
        int nsrc = (i + 1 < cnt) ? g_csrc[beg + i + 1] : 0;
        float e8 = 0.f;
        if (lane < 8) {
            float s = g_asrc[src * 8 + lane] + ad;
            s = (s > 0.f) ? s : 0.2f * s;
            e8 = __expf(s);
            dsum += e8;
        }
        float w2 = __shfl_sync(0xffffffffu, e8, lane >> 2);
        float4 sv = xh4[src * 32 + lane];
        acc.x += w2 * sv.x;
        acc.y += w2 * sv.y;
        acc.z += w2 * sv.z;
        acc.w += w2 * sv.w;
        src = nsrc;
    }

    float dv = __shfl_sync(0xffffffffu, dsum, lane >> 2);
    float inv = 1.0f / dv;
    float4 bv = reinterpret_cast<const float4*>(bias)[lane];
    float4 o = {acc.x * inv + bv.x, acc.y * inv + bv.y,
                acc.z * inv + bv.z, acc.w * inv + bv.w};
    reinterpret_cast<float4*>(out)[node * 32 + lane] = o;
}

// ---------------------------------------------------------------------------
extern "C" void kernel_launch(void* const* d_in, const int* in_sizes, int n_in,
                              void* d_out, int out_size) {
    const float* x     = (const float*)d_in[0];
    const int*   ei    = (const int*)  d_in[1];
    const float* W     = (const float*)d_in[2];
    const float* bproj = (const float*)d_in[3];
    const float* att_s = (const float*)d_in[4];
    const float* att_d = (const float*)d_in[5];
    const float* bias  = (const float*)d_in[6];
    float* out = (float*)d_out;

    const int n = in_sizes[0] / 128;
    const int E = in_sizes[1] / 2;
    const int nb = (n + 1023) >> 10;   // scan blocks (<=128)

    gemm_kernel<<<(n + 63) / 64, 256>>>(x, W, bproj, n);
    att_kernel<<<(n * 8 + 255) / 256, 256>>>(att_s, att_d, n);
    zero_kernel<<<(n + 255) / 256, 256>>>(n);
    hist_kernel<<<(E + 255) / 256, 256>>>(ei, E);
    scan1_kernel<<<nb, 256>>>(n);
    scan2_kernel<<<1, 128>>>(nb);
    scan3_kernel<<<(n + 255) / 256, 256>>>(n);
    fill_kernel<<<(E + 255) / 256, 256>>>(ei, E);
    gather_kernel<<<(n * 32 + 255) / 256, 256>>>(bias, out, n);
}

// round 4
// speedup vs baseline: 2.4894x; 1.2553x over previous
#include <cuda_runtime.h>

// Problem constants: N=100000, E=1600000, DIM=128, HEADS=8, HEAD_DIM=16
#define NMAX 100000
#define EMAX 1600000

static __device__ float g_xh[NMAX * 128];      // projected features [N,128]
static __device__ float g_asrc[NMAX * 8];      // per-node src logits [N,H]
static __device__ float g_adst[NMAX * 8];      // per-node dst logits [N,H]
static __device__ int   g_cnt[NMAX];           // in-degree
static __device__ int   g_off[NMAX];           // CSR offsets
static __device__ int   g_bsum[128];           // scan block sums
static __device__ int   g_epos[EMAX];          // within-segment position per edge
static __device__ int   g_csrc[EMAX];          // CSR: src per dst-sorted edge

// ---------------------------------------------------------------------------
__device__ __forceinline__ void ffma2(unsigned long long& d, unsigned long long a,
                                      unsigned long long b, unsigned long long c) {
    asm("fma.rn.f32x2 %0, %1, %2, %3;" : "=l"(d) : "l"(a), "l"(b), "l"(c));
}
__device__ __forceinline__ unsigned long long dup2(float v) {
    unsigned long long r;
    asm("mov.b64 %0, {%1, %1};" : "=l"(r) : "f"(v));
    return r;
}
__device__ __forceinline__ float2 unpk2(unsigned long long v) {
    float2 f;
    asm("mov.b64 {%0, %1}, %2;" : "=f"(f.x), "=f"(f.y) : "l"(v));
    return f;
}

// ---------------------------------------------------------------------------
// Kernel 1: xh = x @ W^T + b_proj (f32x2 packed FMA) + fused attention logits.
// Block tile 64x128, 256 threads. Epilogue computes per-(row,head) dots with
// att_src/att_dst via intra-4-lane shfl reduction (head h = tx>>2).
// ---------------------------------------------------------------------------
__global__ __launch_bounds__(256) void gemm_kernel(const float* __restrict__ x,
                                                   const float* __restrict__ W,
                                                   const float* __restrict__ b,
                                                   const float* __restrict__ att_s,
                                                   const float* __restrict__ att_d,
                                                   int n) {
    __shared__ float xs[32 * 66];    // [k][row]
    __shared__ float wt[32 * 132];   // [k][c]

    const int t  = threadIdx.x;
    const int tx = t & 31;
    const int ty = t >> 5;
    const int row0 = blockIdx.x * 64;

    unsigned long long acc[4][4];
#pragma unroll
    for (int p = 0; p < 4; p++)
#pragma unroll
        for (int j = 0; j < 4; j++) acc[p][j] = 0ULL;

    for (int kt = 0; kt < 4; kt++) {
        const int k0 = kt * 32;
#pragma unroll
        for (int i = 0; i < 8; i++) {
            int idx = t + i * 256;
            int r = idx >> 5, k = idx & 31;
            int row = row0 + r;
            xs[k * 66 + r] = (row < n) ? x[row * 128 + k0 + k] : 0.f;
        }
#pragma unroll
        for (int i = 0; i < 16; i++) {
            int idx = t + i * 256;
            int c = idx >> 5, k = idx & 31;
            wt[k * 132 + c] = W[c * 128 + k0 + k];
        }
        __syncthreads();
#pragma unroll
        for (int k = 0; k < 32; k++) {
            float4 w4 = *reinterpret_cast<const float4*>(&wt[k * 132 + tx * 4]);
            unsigned long long wd0 = dup2(w4.x), wd1 = dup2(w4.y);
            unsigned long long wd2 = dup2(w4.z), wd3 = dup2(w4.w);
#pragma unroll
            for (int p = 0; p < 4; p++) {
                unsigned long long xp =
                    *reinterpret_cast<const unsigned long long*>(&xs[k * 66 + ty * 8 + p * 2]);
                ffma2(acc[p][0], xp, wd0, acc[p][0]);
                ffma2(acc[p][1], xp, wd1, acc[p][1]);
                ffma2(acc[p][2], xp, wd2, acc[p][2]);
                ffma2(acc[p][3], xp, wd3, acc[p][3]);
            }
        }
        __syncthreads();
    }

    float4 bb  = *reinterpret_cast<const float4*>(&b[tx * 4]);
    float4 as4 = *reinterpret_cast<const float4*>(&att_s[tx * 4]);
    float4 ad4 = *reinterpret_cast<const float4*>(&att_d[tx * 4]);
    const int h = tx >> 2;

#pragma unroll
    for (int p = 0; p < 4; p++) {
        float2 a0 = unpk2(acc[p][0]), a1 = unpk2(acc[p][1]);
        float2 a2 = unpk2(acc[p][2]), a3 = unpk2(acc[p][3]);
#pragma unroll
        for (int half = 0; half < 2; half++) {
            int row = row0 + ty * 8 + p * 2 + half;
            float4 o;
            if (half == 0) o = make_float4(a0.x + bb.x, a1.x + bb.y, a2.x + bb.z, a3.x + bb.w);
            else           o = make_float4(a0.y + bb.x, a1.y + bb.y, a2.y + bb.z, a3.y + bb.w);
            bool valid = (row < n);
            if (valid)
                *reinterpret_cast<float4*>(&g_xh[row * 128 + tx * 4]) = o;
            // fused per-head attention logits
            float ps = o.x * as4.x + o.y * as4.y + o.z * as4.z + o.w * as4.w;
            float pd = o.x * ad4.x + o.y * ad4.y + o.z * ad4.z + o.w * ad4.w;
            ps += __shfl_xor_sync(0xffffffffu, ps, 1);
            ps += __shfl_xor_sync(0xffffffffu, ps, 2);
            pd += __shfl_xor_sync(0xffffffffu, pd, 1);
            pd += __shfl_xor_sync(0xffffffffu, pd, 2);
            if (valid && (tx & 3) == 0) {
                g_asrc[row * 8 + h] = ps;
                g_adst[row * 8 + h] = pd;
            }
        }
    }
}

// ---------------------------------------------------------------------------
// CSR construction
// ---------------------------------------------------------------------------
__global__ __launch_bounds__(256) void zero_kernel(int n) {
    int t = blockIdx.x * 256 + threadIdx.x;
    if (t < n) g_cnt[t] = 0;
}

// histogram; also record this edge's position within its destination segment
__global__ __launch_bounds__(256) void hist_kernel(const int* __restrict__ ei, int E) {
    int e = blockIdx.x * 256 + threadIdx.x;
    if (e < E) g_epos[e] = atomicAdd(&g_cnt[ei[E + e]], 1);
}

__global__ __launch_bounds__(256) void scan1_kernel(int n) {
    __shared__ int s[256];
    int b = blockIdx.x, t = threadIdx.x;
    int base = b * 1024 + t * 4;
    int v[4];
#pragma unroll
    for (int j = 0; j < 4; j++) v[j] = (base + j < n) ? g_cnt[base + j] : 0;
    int local = v[0] + v[1] + v[2] + v[3];
    s[t] = local;
    __syncthreads();
    for (int off = 1; off < 256; off <<= 1) {
        int xv = (t >= off) ? s[t - off] : 0;
        __syncthreads();
        s[t] += xv;
        __syncthreads();
    }
    int run = s[t] - local;
#pragma unroll
    for (int j = 0; j < 4; j++) {
        if (base + j < n) g_off[base + j] = run;
        run += v[j];
    }
    if (t == 255) g_bsum[b] = s[255];
}

__global__ __launch_bounds__(128) void scan2_kernel(int nb) {
    __shared__ int s[128];
    int t = threadIdx.x;
    int v = (t < nb) ? g_bsum[t] : 0;
    s[t] = v;
    __syncthreads();
    for (int off = 1; off < 128; off <<= 1) {
        int xv = (t >= off) ? s[t - off] : 0;
        __syncthreads();
        s[t] += xv;
        __syncthreads();
    }
    if (t < nb) g_bsum[t] = s[t] - v;
}

__global__ __launch_bounds__(256) void scan3_kernel(int n) {
    int t = blockIdx.x * 256 + threadIdx.x;
    if (t < n) g_off[t] += g_bsum[t >> 10];
}

// atomic-free fill using precomputed positions
__global__ __launch_bounds__(256) void fill_kernel(const int* __restrict__ ei, int E) {
    int e = blockIdx.x * 256 + threadIdx.x;
    if (e >= E) return;
    g_csrc[g_off[ei[E + e]] + g_epos[e]] = ei[e];
}

// ---------------------------------------------------------------------------
// Fused gather: one warp per destination node. No shfl: each lane loads the
// logit of its own head (4-lane broadcast) and keeps a replicated dsum.
// 4-edge batching for memory-level parallelism.
// ---------------------------------------------------------------------------
__global__ __launch_bounds__(256) void gather_kernel(const float* __restrict__ bias,
                                                     float* __restrict__ out, int n) {
    int gt = blockIdx.x * 256 + threadIdx.x;
    int node = gt >> 5, lane = gt & 31;
    if (node >= n) return;
    const float4* xh4 = reinterpret_cast<const float4*>(g_xh);
    const int hoff = lane >> 2;   // head index for this lane

    float ad = __ldg(&g_adst[node * 8 + hoff]);
    float s0 = __ldg(&g_asrc[node * 8 + hoff]) + ad;
    s0 = (s0 > 0.f) ? s0 : 0.2f * s0;
    float ex = __expf(s0);
    float dsum = ex;
    float4 xv = xh4[node * 32 + lane];
    float4 acc = {ex * xv.x, ex * xv.y, ex * xv.z, ex * xv.w};

    const int beg = g_off[node], cnt = g_cnt[node];
    int i = 0;
    for (; i + 4 <= cnt; i += 4) {
        int sA = __ldg(&g_csrc[beg + i]);
        int sB = __ldg(&g_csrc[beg + i + 1]);
        int sC = __ldg(&g_csrc[beg + i + 2]);
        int sD = __ldg(&g_csrc[beg + i + 3]);
        float aA = __ldg(&g_asrc[sA * 8 + hoff]);
        float aB = __ldg(&g_asrc[sB * 8 + hoff]);
        float aC = __ldg(&g_asrc[sC * 8 + hoff]);
        float aD = __ldg(&g_asrc[sD * 8 + hoff]);
        float4 vA = xh4[sA * 32 + lane];
        float4 vB = xh4[sB * 32 + lane];
        float4 vC = xh4[sC * 32 + lane];
        float4 vD = xh4[sD * 32 + lane];
        float tA = aA + ad; tA = (tA > 0.f) ? tA : 0.2f * tA;
        float tB = aB + ad; tB = (tB > 0.f) ? tB : 0.2f * tB;
        float tC = aC + ad; tC = (tC > 0.f) ? tC : 0.2f * tC;
        float tD = aD + ad; tD = (tD > 0.f) ? tD : 0.2f * tD;
        float eA = __expf(tA), eB = __expf(tB), eC = __expf(tC), eD = __expf(tD);
        dsum += eA + eB + eC + eD;
        acc.x += eA * vA.x + eB * vB.x + eC * vC.x + eD * vD.x;
        acc.y += eA * vA.y + eB * vB.y + eC * vC.y + eD * vD.y;
        acc.z += eA * vA.z + eB * vB.z + eC * vC.z + eD * vD.z;
        acc.w += eA * vA.w + eB * vB.w + eC * vC.w + eD * vD.w;
    }
    for (; i < cnt; i++) {
        int s = __ldg(&g_csrc[beg + i]);
        float a = __ldg(&g_asrc[s * 8 + hoff]) + ad;
        a = (a > 0.f) ? a : 0.2f * a;
        float e = __expf(a);
        dsum += e;
        float4 v = xh4[s * 32 + lane];
        acc.x += e * v.x; acc.y += e * v.y; acc.z += e * v.z; acc.w += e * v.w;
    }

    float inv = 1.0f / dsum;
    float4 bv = reinterpret_cast<const float4*>(bias)[lane];
    float4 o = {acc.x * inv + bv.x, acc.y * inv + bv.y,
                acc.z * inv + bv.z, acc.w * inv + bv.w};
    reinterpret_cast<float4*>(out)[node * 32 + lane] = o;
}

// ---------------------------------------------------------------------------
extern "C" void kernel_launch(void* const* d_in, const int* in_sizes, int n_in,
                              void* d_out, int out_size) {
    const float* x     = (const float*)d_in[0];
    const int*   ei    = (const int*)  d_in[1];
    const float* W     = (const float*)d_in[2];
    const float* bproj = (const float*)d_in[3];
    const float* att_s = (const float*)d_in[4];
    const float* att_d = (const float*)d_in[5];
    const float* bias  = (const float*)d_in[6];
    float* out = (float*)d_out;

    const int n = in_sizes[0] / 128;
    const int E = in_sizes[1] / 2;
    const int nb = (n + 1023) >> 10;

    // lazily-created side stream + events (first call is the uncaptured
    // correctness run; subsequent captured calls reuse them)
    static cudaStream_t s_csr = nullptr;
    static cudaEvent_t ev_fork = nullptr, ev_join = nullptr;
    if (!s_csr) {
        cudaStreamCreateWithFlags(&s_csr, cudaStreamNonBlocking);
        cudaEventCreateWithFlags(&ev_fork, cudaEventDisableTiming);
        cudaEventCreateWithFlags(&ev_join, cudaEventDisableTiming);
    }

    // fork: CSR build runs concurrently with GEMM (+fused att logits)
    cudaEventRecord(ev_fork, 0);
    cudaStreamWaitEvent(s_csr, ev_fork, 0);
    zero_kernel<<<(n + 255) / 256, 256, 0, s_csr>>>(n);
    hist_kernel<<<(E + 255) / 256, 256, 0, s_csr>>>(ei, E);
    scan1_kernel<<<nb, 256, 0, s_csr>>>(n);
    scan2_kernel<<<1, 128, 0, s_csr>>>(nb);
    scan3_kernel<<<(n + 255) / 256, 256, 0, s_csr>>>(n);
    fill_kernel<<<(E + 255) / 256, 256, 0, s_csr>>>(ei, E);
    cudaEventRecord(ev_join, s_csr);

    gemm_kernel<<<(n + 63) / 64, 256>>>(x, W, bproj, att_s, att_d, n);

    // join: gather needs both CSR and xh/logits
    cudaStreamWaitEvent(0, ev_join, 0);
    gather_kernel<<<(n * 32 + 255) / 256, 256>>>(bias, out, n);
}

// round 5
// speedup vs baseline: 2.6247x; 1.0543x over previous
#include <cuda_runtime.h>
#include <cuda_fp16.h>

// Problem constants: N=100000, E=1600000, DIM=128, HEADS=8, HEAD_DIM=16
#define NMAX 100000
#define EMAX 1600000

static __device__ __half g_xh_h[NMAX * 128];   // projected features, fp16 [N,128]
static __device__ float  g_asrc[NMAX * 8];     // per-node src logits [N,H]
static __device__ float  g_adst[NMAX * 8];     // per-node dst logits [N,H]
static __device__ int    g_cnt[NMAX];          // in-degree
static __device__ int    g_off[NMAX];          // CSR offsets
static __device__ int    g_bsum[128];          // scan block sums
static __device__ int    g_epos[EMAX];         // within-segment position per edge
static __device__ int    g_csrc[EMAX];         // CSR: src per dst-sorted edge

// ---------------------------------------------------------------------------
__device__ __forceinline__ void ffma2(unsigned long long& d, unsigned long long a,
                                      unsigned long long b, unsigned long long c) {
    asm("fma.rn.f32x2 %0, %1, %2, %3;" : "=l"(d) : "l"(a), "l"(b), "l"(c));
}
__device__ __forceinline__ unsigned long long dup2(float v) {
    unsigned long long r;
    asm("mov.b64 %0, {%1, %1};" : "=l"(r) : "f"(v));
    return r;
}
__device__ __forceinline__ float2 unpk2(unsigned long long v) {
    float2 f;
    asm("mov.b64 {%0, %1}, %2;" : "=f"(f.x), "=f"(f.y) : "l"(v));
    return f;
}

// ---------------------------------------------------------------------------
// Kernel 1: xh = x @ W^T + b_proj (f32x2 packed FMA), epilogue:
//  - store xh as fp16 (halves gather traffic)
//  - fused per-(row,head) attention logits (fp32, intra-4-lane shfl reduce)
// ---------------------------------------------------------------------------
__global__ __launch_bounds__(256) void gemm_kernel(const float* __restrict__ x,
                                                   const float* __restrict__ W,
                                                   const float* __restrict__ b,
                                                   const float* __restrict__ att_s,
                                                   const float* __restrict__ att_d,
                                                   int n) {
    __shared__ float xs[32 * 66];    // [k][row]
    __shared__ float wt[32 * 132];   // [k][c]

    const int t  = threadIdx.x;
    const int tx = t & 31;
    const int ty = t >> 5;
    const int row0 = blockIdx.x * 64;

    unsigned long long acc[4][4];
#pragma unroll
    for (int p = 0; p < 4; p++)
#pragma unroll
        for (int j = 0; j < 4; j++) acc[p][j] = 0ULL;

    for (int kt = 0; kt < 4; kt++) {
        const int k0 = kt * 32;
#pragma unroll
        for (int i = 0; i < 8; i++) {
            int idx = t + i * 256;
            int r = idx >> 5, k = idx & 31;
            int row = row0 + r;
            xs[k * 66 + r] = (row < n) ? x[row * 128 + k0 + k] : 0.f;
        }
#pragma unroll
        for (int i = 0; i < 16; i++) {
            int idx = t + i * 256;
            int c = idx >> 5, k = idx & 31;
            wt[k * 132 + c] = W[c * 128 + k0 + k];
        }
        __syncthreads();
#pragma unroll
        for (int k = 0; k < 32; k++) {
            float4 w4 = *reinterpret_cast<const float4*>(&wt[k * 132 + tx * 4]);
            unsigned long long wd0 = dup2(w4.x), wd1 = dup2(w4.y);
            unsigned long long wd2 = dup2(w4.z), wd3 = dup2(w4.w);
#pragma unroll
            for (int p = 0; p < 4; p++) {
                unsigned long long xp =
                    *reinterpret_cast<const unsigned long long*>(&xs[k * 66 + ty * 8 + p * 2]);
                ffma2(acc[p][0], xp, wd0, acc[p][0]);
                ffma2(acc[p][1], xp, wd1, acc[p][1]);
                ffma2(acc[p][2], xp, wd2, acc[p][2]);
                ffma2(acc[p][3], xp, wd3, acc[p][3]);
            }
        }
        __syncthreads();
    }

    float4 bb  = *reinterpret_cast<const float4*>(&b[tx * 4]);
    float4 as4 = *reinterpret_cast<const float4*>(&att_s[tx * 4]);
    float4 ad4 = *reinterpret_cast<const float4*>(&att_d[tx * 4]);
    const int h = tx >> 2;

#pragma unroll
    for (int p = 0; p < 4; p++) {
        float2 a0 = unpk2(acc[p][0]), a1 = unpk2(acc[p][1]);
        float2 a2 = unpk2(acc[p][2]), a3 = unpk2(acc[p][3]);
#pragma unroll
        for (int half = 0; half < 2; half++) {
            int row = row0 + ty * 8 + p * 2 + half;
            float4 o;
            if (half == 0) o = make_float4(a0.x + bb.x, a1.x + bb.y, a2.x + bb.z, a3.x + bb.w);
            else           o = make_float4(a0.y + bb.x, a1.y + bb.y, a2.y + bb.z, a3.y + bb.w);
            bool valid = (row < n);
            if (valid) {
                union { __half2 h2[2]; uint2 u; } pk;
                pk.h2[0] = __floats2half2_rn(o.x, o.y);
                pk.h2[1] = __floats2half2_rn(o.z, o.w);
                *reinterpret_cast<uint2*>(&g_xh_h[row * 128 + tx * 4]) = pk.u;
            }
            float ps = o.x * as4.x + o.y * as4.y + o.z * as4.z + o.w * as4.w;
            float pd = o.x * ad4.x + o.y * ad4.y + o.z * ad4.z + o.w * ad4.w;
            ps += __shfl_xor_sync(0xffffffffu, ps, 1);
            ps += __shfl_xor_sync(0xffffffffu, ps, 2);
            pd += __shfl_xor_sync(0xffffffffu, pd, 1);
            pd += __shfl_xor_sync(0xffffffffu, pd, 2);
            if (valid && (tx & 3) == 0) {
                g_asrc[row * 8 + h] = ps;
                g_adst[row * 8 + h] = pd;
            }
        }
    }
}

// ---------------------------------------------------------------------------
// CSR construction
// ---------------------------------------------------------------------------
__global__ __launch_bounds__(256) void zero_kernel(int n) {
    int t = blockIdx.x * 256 + threadIdx.x;
    if (t < n) g_cnt[t] = 0;
}

__global__ __launch_bounds__(256) void hist_kernel(const int* __restrict__ ei, int E) {
    int e = blockIdx.x * 256 + threadIdx.x;
    if (e < E) g_epos[e] = atomicAdd(&g_cnt[ei[E + e]], 1);
}

// per-1024-block exclusive scan + block totals
__global__ __launch_bounds__(256) void scan1_kernel(int n) {
    __shared__ int s[256];
    int b = blockIdx.x, t = threadIdx.x;
    int base = b * 1024 + t * 4;
    int v[4];
#pragma unroll
    for (int j = 0; j < 4; j++) v[j] = (base + j < n) ? g_cnt[base + j] : 0;
    int local = v[0] + v[1] + v[2] + v[3];
    s[t] = local;
    __syncthreads();
    for (int off = 1; off < 256; off <<= 1) {
        int xv = (t >= off) ? s[t - off] : 0;
        __syncthreads();
        s[t] += xv;
        __syncthreads();
    }
    int run = s[t] - local;
#pragma unroll
    for (int j = 0; j < 4; j++) {
        if (base + j < n) g_off[base + j] = run;
        run += v[j];
    }
    if (t == 255) g_bsum[b] = s[255];
}

// fused: each block redundantly prefix-sums block totals, applies its offset
__global__ __launch_bounds__(256) void scan3_kernel(int n, int nb) {
    __shared__ int s[128];
    int b = blockIdx.x, t = threadIdx.x;
    if (t < 128) s[t] = (t < b) ? g_bsum[t] : 0;   // only blocks before b
    __syncthreads();
    // reduce 128 -> 1 (sum of preceding block totals)
    if (t < 64) s[t] += s[t + 64];
    __syncthreads();
    if (t < 32) {
        int v = s[t] + s[t + 32];
        v += __shfl_down_sync(0xffffffffu, v, 16);
        v += __shfl_down_sync(0xffffffffu, v, 8);
        v += __shfl_down_sync(0xffffffffu, v, 4);
        v += __shfl_down_sync(0xffffffffu, v, 2);
        v += __shfl_down_sync(0xffffffffu, v, 1);
        if (t == 0) s[0] = v;
    }
    __syncthreads();
    int add = s[0];
    int base = b * 1024 + t * 4;
#pragma unroll
    for (int j = 0; j < 4; j++)
        if (base + j < n) g_off[base + j] += add;
}

__global__ __launch_bounds__(256) void fill_kernel(const int* __restrict__ ei, int E) {
    int e = blockIdx.x * 256 + threadIdx.x;
    if (e >= E) return;
    g_csrc[g_off[ei[E + e]] + g_epos[e]] = ei[e];
}

// ---------------------------------------------------------------------------
// Fused gather (fp16 features): one warp per destination node, lane l owns
// halfs [4l..4l+3] (head l>>2). No shuffles: per-lane head logit loads are
// 4-lane broadcasts; dsum replicated per lane. 4-edge batching for MLP.
// ---------------------------------------------------------------------------
__global__ __launch_bounds__(256) void gather_kernel(const float* __restrict__ bias,
                                                     float* __restrict__ out, int n) {
    int gt = blockIdx.x * 256 + threadIdx.x;
    int node = gt >> 5, lane = gt & 31;
    if (node >= n) return;
    const uint2* xh2 = reinterpret_cast<const uint2*>(g_xh_h);   // 32 uint2 per row
    const int hoff = lane >> 2;

    float ad = __ldg(&g_adst[node * 8 + hoff]);
    float s0 = __ldg(&g_asrc[node * 8 + hoff]) + ad;
    s0 = (s0 > 0.f) ? s0 : 0.2f * s0;
    float ex = __expf(s0);
    float dsum = ex;

    uint2 sv = xh2[node * 32 + lane];
    float2 f0 = __half22float2(*reinterpret_cast<__half2*>(&sv.x));
    float2 f1 = __half22float2(*reinterpret_cast<__half2*>(&sv.y));
    float4 acc = {ex * f0.x, ex * f0.y, ex * f1.x, ex * f1.y};

    const int beg = __ldg(&g_off[node]), cnt = __ldg(&g_cnt[node]);
    int i = 0;
    for (; i + 4 <= cnt; i += 4) {
        int sA = __ldg(&g_csrc[beg + i]);
        int sB = __ldg(&g_csrc[beg + i + 1]);
        int sC = __ldg(&g_csrc[beg + i + 2]);
        int sD = __ldg(&g_csrc[beg + i + 3]);
        float aA = __ldg(&g_asrc[sA * 8 + hoff]);
        float aB = __ldg(&g_asrc[sB * 8 + hoff]);
        float aC = __ldg(&g_asrc[sC * 8 + hoff]);
        float aD = __ldg(&g_asrc[sD * 8 + hoff]);
        uint2 vA = xh2[sA * 32 + lane];
        uint2 vB = xh2[sB * 32 + lane];
        uint2 vC = xh2[sC * 32 + lane];
        uint2 vD = xh2[sD * 32 + lane];
        float tA = aA + ad; tA = (tA > 0.f) ? tA : 0.2f * tA;
        float tB = aB + ad; tB = (tB > 0.f) ? tB : 0.2f * tB;
        float tC = aC + ad; tC = (tC > 0.f) ? tC : 0.2f * tC;
        float tD = aD + ad; tD = (tD > 0.f) ? tD : 0.2f * tD;
        float eA = __expf(tA), eB = __expf(tB), eC = __expf(tC), eD = __expf(tD);
        dsum += eA + eB + eC + eD;
        float2 a0 = __half22float2(*reinterpret_cast<__half2*>(&vA.x));
        float2 a1 = __half22float2(*reinterpret_cast<__half2*>(&vA.y));
        float2 b0 = __half22float2(*reinterpret_cast<__half2*>(&vB.x));
        float2 b1 = __half22float2(*reinterpret_cast<__half2*>(&vB.y));
        float2 c0 = __half22float2(*reinterpret_cast<__half2*>(&vC.x));
        float2 c1 = __half22float2(*reinterpret_cast<__half2*>(&vC.y));
        float2 d0 = __half22float2(*reinterpret_cast<__half2*>(&vD.x));
        float2 d1 = __half22float2(*reinterpret_cast<__half2*>(&vD.y));
        acc.x += eA * a0.x + eB * b0.x + eC * c0.x + eD * d0.x;
        acc.y += eA * a0.y + eB * b0.y + eC * c0.y + eD * d0.y;
        acc.z += eA * a1.x + eB * b1.x + eC * c1.x + eD * d1.x;
        acc.w += eA * a1.y + eB * b1.y + eC * c1.y + eD * d1.y;
    }
    for (; i < cnt; i++) {
        int s = __ldg(&g_csrc[beg + i]);
        float a = __ldg(&g_asrc[s * 8 + hoff]) + ad;
        a = (a > 0.f) ? a : 0.2f * a;
        float e = __expf(a);
        dsum += e;
        uint2 v = xh2[s * 32 + lane];
        float2 p0 = __half22float2(*reinterpret_cast<__half2*>(&v.x));
        float2 p1 = __half22float2(*reinterpret_cast<__half2*>(&v.y));
        acc.x += e * p0.x; acc.y += e * p0.y; acc.z += e * p1.x; acc.w += e * p1.y;
    }

    float inv = 1.0f / dsum;
    float4 bv = reinterpret_cast<const float4*>(bias)[lane];
    float4 o = {acc.x * inv + bv.x, acc.y * inv + bv.y,
                acc.z * inv + bv.z, acc.w * inv + bv.w};
    reinterpret_cast<float4*>(out)[node * 32 + lane] = o;
}

// ---------------------------------------------------------------------------
extern "C" void kernel_launch(void* const* d_in, const int* in_sizes, int n_in,
                              void* d_out, int out_size) {
    const float* x     = (const float*)d_in[0];
    const int*   ei    = (const int*)  d_in[1];
    const float* W     = (const float*)d_in[2];
    const float* bproj = (const float*)d_in[3];
    const float* att_s = (const float*)d_in[4];
    const float* att_d = (const float*)d_in[5];
    const float* bias  = (const float*)d_in[6];
    float* out = (float*)d_out;

    const int n = in_sizes[0] / 128;
    const int E = in_sizes[1] / 2;
    const int nb = (n + 1023) >> 10;

    static cudaStream_t s_csr = nullptr;
    static cudaEvent_t ev_fork = nullptr, ev_join = nullptr;
    if (!s_csr) {
        cudaStreamCreateWithFlags(&s_csr, cudaStreamNonBlocking);
        cudaEventCreateWithFlags(&ev_fork, cudaEventDisableTiming);
        cudaEventCreateWithFlags(&ev_join, cudaEventDisableTiming);
    }

    // fork: CSR build overlaps GEMM (+fused logits)
    cudaEventRecord(ev_fork, 0);
    cudaStreamWaitEvent(s_csr, ev_fork, 0);
    zero_kernel<<<(n + 255) / 256, 256, 0, s_csr>>>(n);
    hist_kernel<<<(E + 255) / 256, 256, 0, s_csr>>>(ei, E);
    scan1_kernel<<<nb, 256, 0, s_csr>>>(n);
    scan3_kernel<<<nb, 256, 0, s_csr>>>(n, nb);
    fill_kernel<<<(E + 255) / 256, 256, 0, s_csr>>>(ei, E);
    cudaEventRecord(ev_join, s_csr);

    gemm_kernel<<<(n + 63) / 64, 256>>>(x, W, bproj, att_s, att_d, n);

    cudaStreamWaitEvent(0, ev_join, 0);
    gather_kernel<<<(n * 32 + 255) / 256, 256>>>(bias, out, n);
}

// round 6
// speedup vs baseline: 2.6859x; 1.0233x over previous
#include <cuda_runtime.h>
#include <cuda_fp16.h>

// Problem constants: N=100000, E=1600000, DIM=128, HEADS=8, HEAD_DIM=16
#define NMAX 100000
#define EMAX 1600000

static __device__ __half g_xh_h[NMAX * 128];   // projected features, fp16 [N,128]
static __device__ float  g_asrc[NMAX * 8];     // per-node src logits [N,H]
static __device__ float  g_adst[NMAX * 8];     // per-node dst logits [N,H]
static __device__ int    g_cnt[NMAX];          // in-degree
static __device__ int    g_off[NMAX];          // CSR offsets
static __device__ int    g_bsum[128];          // scan block sums
static __device__ int    g_epos[EMAX];         // within-segment position per edge
static __device__ int    g_csrc[EMAX];         // CSR: src per dst-sorted edge

// ---------------------------------------------------------------------------
__device__ __forceinline__ void ffma2(unsigned long long& d, unsigned long long a,
                                      unsigned long long b, unsigned long long c) {
    asm("fma.rn.f32x2 %0, %1, %2, %3;" : "=l"(d) : "l"(a), "l"(b), "l"(c));
}
__device__ __forceinline__ unsigned long long dup2(float v) {
    unsigned long long r;
    asm("mov.b64 %0, {%1, %1};" : "=l"(r) : "f"(v));
    return r;
}
__device__ __forceinline__ float2 unpk2(unsigned long long v) {
    float2 f;
    asm("mov.b64 {%0, %1}, %2;" : "=f"(f.x), "=f"(f.y) : "l"(v));
    return f;
}

// ---------------------------------------------------------------------------
// Kernel 1: xh = x @ W^T + b_proj (f32x2 packed FMA); epilogue stores fp16 xh
// and fused per-(row,head) attention logits.
// ---------------------------------------------------------------------------
__global__ __launch_bounds__(256) void gemm_kernel(const float* __restrict__ x,
                                                   const float* __restrict__ W,
                                                   const float* __restrict__ b,
                                                   const float* __restrict__ att_s,
                                                   const float* __restrict__ att_d,
                                                   int n) {
    __shared__ float xs[32 * 66];    // [k][row]
    __shared__ float wt[32 * 132];   // [k][c]

    const int t  = threadIdx.x;
    const int tx = t & 31;
    const int ty = t >> 5;
    const int row0 = blockIdx.x * 64;

    unsigned long long acc[4][4];
#pragma unroll
    for (int p = 0; p < 4; p++)
#pragma unroll
        for (int j = 0; j < 4; j++) acc[p][j] = 0ULL;

    for (int kt = 0; kt < 4; kt++) {
        const int k0 = kt * 32;
#pragma unroll
        for (int i = 0; i < 8; i++) {
            int idx = t + i * 256;
            int r = idx >> 5, k = idx & 31;
            int row = row0 + r;
            xs[k * 66 + r] = (row < n) ? x[row * 128 + k0 + k] : 0.f;
        }
#pragma unroll
        for (int i = 0; i < 16; i++) {
            int idx = t + i * 256;
            int c = idx >> 5, k = idx & 31;
            wt[k * 132 + c] = W[c * 128 + k0 + k];
        }
        __syncthreads();
#pragma unroll
        for (int k = 0; k < 32; k++) {
            float4 w4 = *reinterpret_cast<const float4*>(&wt[k * 132 + tx * 4]);
            unsigned long long wd0 = dup2(w4.x), wd1 = dup2(w4.y);
            unsigned long long wd2 = dup2(w4.z), wd3 = dup2(w4.w);
#pragma unroll
            for (int p = 0; p < 4; p++) {
                unsigned long long xp =
                    *reinterpret_cast<const unsigned long long*>(&xs[k * 66 + ty * 8 + p * 2]);
                ffma2(acc[p][0], xp, wd0, acc[p][0]);
                ffma2(acc[p][1], xp, wd1, acc[p][1]);
                ffma2(acc[p][2], xp, wd2, acc[p][2]);
                ffma2(acc[p][3], xp, wd3, acc[p][3]);
            }
        }
        __syncthreads();
    }

    float4 bb  = *reinterpret_cast<const float4*>(&b[tx * 4]);
    float4 as4 = *reinterpret_cast<const float4*>(&att_s[tx * 4]);
    float4 ad4 = *reinterpret_cast<const float4*>(&att_d[tx * 4]);
    const int h = tx >> 2;

#pragma unroll
    for (int p = 0; p < 4; p++) {
        float2 a0 = unpk2(acc[p][0]), a1 = unpk2(acc[p][1]);
        float2 a2 = unpk2(acc[p][2]), a3 = unpk2(acc[p][3]);
#pragma unroll
        for (int half = 0; half < 2; half++) {
            int row = row0 + ty * 8 + p * 2 + half;
            float4 o;
            if (half == 0) o = make_float4(a0.x + bb.x, a1.x + bb.y, a2.x + bb.z, a3.x + bb.w);
            else           o = make_float4(a0.y + bb.x, a1.y + bb.y, a2.y + bb.z, a3.y + bb.w);
            bool valid = (row < n);
            if (valid) {
                union { __half2 h2[2]; uint2 u; } pk;
                pk.h2[0] = __floats2half2_rn(o.x, o.y);
                pk.h2[1] = __floats2half2_rn(o.z, o.w);
                *reinterpret_cast<uint2*>(&g_xh_h[row * 128 + tx * 4]) = pk.u;
            }
            float ps = o.x * as4.x + o.y * as4.y + o.z * as4.z + o.w * as4.w;
            float pd = o.x * ad4.x + o.y * ad4.y + o.z * ad4.z + o.w * ad4.w;
            ps += __shfl_xor_sync(0xffffffffu, ps, 1);
            ps += __shfl_xor_sync(0xffffffffu, ps, 2);
            pd += __shfl_xor_sync(0xffffffffu, pd, 1);
            pd += __shfl_xor_sync(0xffffffffu, pd, 2);
            if (valid && (tx & 3) == 0) {
                g_asrc[row * 8 + h] = ps;
                g_adst[row * 8 + h] = pd;
            }
        }
    }
}

// ---------------------------------------------------------------------------
// CSR construction
// ---------------------------------------------------------------------------
__global__ __launch_bounds__(256) void zero_kernel(int n) {
    int t = blockIdx.x * 256 + threadIdx.x;
    if (t < n) g_cnt[t] = 0;
}

__global__ __launch_bounds__(256) void hist_kernel(const int* __restrict__ ei, int E) {
    int e = blockIdx.x * 256 + threadIdx.x;
    if (e < E) g_epos[e] = atomicAdd(&g_cnt[ei[E + e]], 1);
}

__global__ __launch_bounds__(256) void scan1_kernel(int n) {
    __shared__ int s[256];
    int b = blockIdx.x, t = threadIdx.x;
    int base = b * 1024 + t * 4;
    int v[4];
#pragma unroll
    for (int j = 0; j < 4; j++) v[j] = (base + j < n) ? g_cnt[base + j] : 0;
    int local = v[0] + v[1] + v[2] + v[3];
    s[t] = local;
    __syncthreads();
    for (int off = 1; off < 256; off <<= 1) {
        int xv = (t >= off) ? s[t - off] : 0;
        __syncthreads();
        s[t] += xv;
        __syncthreads();
    }
    int run = s[t] - local;
#pragma unroll
    for (int j = 0; j < 4; j++) {
        if (base + j < n) g_off[base + j] = run;
        run += v[j];
    }
    if (t == 255) g_bsum[b] = s[255];
}

__global__ __launch_bounds__(256) void scan3_kernel(int n, int nb) {
    __shared__ int s[128];
    int b = blockIdx.x, t = threadIdx.x;
    if (t < 128) s[t] = (t < b) ? g_bsum[t] : 0;
    __syncthreads();
    if (t < 64) s[t] += s[t + 64];
    __syncthreads();
    if (t < 32) {
        int v = s[t] + s[t + 32];
        v += __shfl_down_sync(0xffffffffu, v, 16);
        v += __shfl_down_sync(0xffffffffu, v, 8);
        v += __shfl_down_sync(0xffffffffu, v, 4);
        v += __shfl_down_sync(0xffffffffu, v, 2);
        v += __shfl_down_sync(0xffffffffu, v, 1);
        if (t == 0) s[0] = v;
    }
    __syncthreads();
    int add = s[0];
    int base = b * 1024 + t * 4;
#pragma unroll
    for (int j = 0; j < 4; j++)
        if (base + j < n) g_off[base + j] += add;
}

__global__ __launch_bounds__(256) void fill_kernel(const int* __restrict__ ei, int E) {
    int e = blockIdx.x * 256 + threadIdx.x;
    if (e >= E) return;
    g_csrc[g_off[ei[E + e]] + g_epos[e]] = ei[e];
}

// ---------------------------------------------------------------------------
// Fused gather: 2 warps per 64-thread CTA, one node per warp.
// Edge indices prefetched per-lane (one csrc load covers 32 edges), then
// distributed by shfl -> all data loads of a chunk are independent (high MLP).
// ---------------------------------------------------------------------------
__global__ __launch_bounds__(64) void gather_kernel(const float* __restrict__ bias,
                                                    float* __restrict__ out, int n) {
    int node = blockIdx.x * 2 + (threadIdx.x >> 5);
    int lane = threadIdx.x & 31;
    if (node >= n) return;
    const uint2* xh2 = reinterpret_cast<const uint2*>(g_xh_h);
    const int hoff = lane >> 2;

    float ad = __ldg(&g_adst[node * 8 + hoff]);
    float s0 = __ldg(&g_asrc[node * 8 + hoff]) + ad;
    s0 = (s0 > 0.f) ? s0 : 0.2f * s0;
    float ex = __expf(s0);
    float dsum = ex;

    uint2 sv = __ldg(&xh2[node * 32 + lane]);
    float2 f0 = __half22float2(*reinterpret_cast<__half2*>(&sv.x));
    float2 f1 = __half22float2(*reinterpret_cast<__half2*>(&sv.y));
    float4 acc = {ex * f0.x, ex * f0.y, ex * f1.x, ex * f1.y};

    const int beg = __ldg(&g_off[node]), cnt = __ldg(&g_cnt[node]);

    for (int c0 = 0; c0 < cnt; c0 += 32) {
        const int rem = min(cnt - c0, 32);
        // one per-lane load covers the whole 32-edge chunk
        int myidx = (lane < rem) ? __ldg(&g_csrc[beg + c0 + lane]) : 0;

        int j = 0;
        for (; j + 4 <= rem; j += 4) {
            int sA = __shfl_sync(0xffffffffu, myidx, j);
            int sB = __shfl_sync(0xffffffffu, myidx, j + 1);
            int sC = __shfl_sync(0xffffffffu, myidx, j + 2);
            int sD = __shfl_sync(0xffffffffu, myidx, j + 3);
            float aA = __ldg(&g_asrc[sA * 8 + hoff]);
            float aB = __ldg(&g_asrc[sB * 8 + hoff]);
            float aC = __ldg(&g_asrc[sC * 8 + hoff]);
            float aD = __ldg(&g_asrc[sD * 8 + hoff]);
            uint2 vA = __ldg(&xh2[sA * 32 + lane]);
            uint2 vB = __ldg(&xh2[sB * 32 + lane]);
            uint2 vC = __ldg(&xh2[sC * 32 + lane]);
            uint2 vD = __ldg(&xh2[sD * 32 + lane]);
            float tA = aA + ad; tA = (tA > 0.f) ? tA : 0.2f * tA;
            float tB = aB + ad; tB = (tB > 0.f) ? tB : 0.2f * tB;
            float tC = aC + ad; tC = (tC > 0.f) ? tC : 0.2f * tC;
            float tD = aD + ad; tD = (tD > 0.f) ? tD : 0.2f * tD;
            float eA = __expf(tA), eB = __expf(tB), eC = __expf(tC), eD = __expf(tD);
            dsum += eA + eB + eC + eD;
            float2 a0 = __half22float2(*reinterpret_cast<__half2*>(&vA.x));
            float2 a1 = __half22float2(*reinterpret_cast<__half2*>(&vA.y));
            float2 b0 = __half22float2(*reinterpret_cast<__half2*>(&vB.x));
            float2 b1 = __half22float2(*reinterpret_cast<__half2*>(&vB.y));
            float2 c4 = __half22float2(*reinterpret_cast<__half2*>(&vC.x));
            float2 c1 = __half22float2(*reinterpret_cast<__half2*>(&vC.y));
            float2 d0 = __half22float2(*reinterpret_cast<__half2*>(&vD.x));
            float2 d1 = __half22float2(*reinterpret_cast<__half2*>(&vD.y));
            acc.x += eA * a0.x + eB * b0.x + eC * c4.x + eD * d0.x;
            acc.y += eA * a0.y + eB * b0.y + eC * c4.y + eD * d0.y;
            acc.z += eA * a1.x + eB * b1.x + eC * c1.x + eD * d1.x;
            acc.w += eA * a1.y + eB * b1.y + eC * c1.y + eD * d1.y;
        }
        for (; j < rem; j++) {
            int s = __shfl_sync(0xffffffffu, myidx, j);
            float a = __ldg(&g_asrc[s * 8 + hoff]) + ad;
            a = (a > 0.f) ? a : 0.2f * a;
            float e = __expf(a);
            dsum += e;
            uint2 v = __ldg(&xh2[s * 32 + lane]);
            float2 p0 = __half22float2(*reinterpret_cast<__half2*>(&v.x));
            float2 p1 = __half22float2(*reinterpret_cast<__half2*>(&v.y));
            acc.x += e * p0.x; acc.y += e * p0.y; acc.z += e * p1.x; acc.w += e * p1.y;
        }
    }

    float inv = 1.0f / dsum;
    float4 bv = reinterpret_cast<const float4*>(bias)[lane];
    float4 o = {acc.x * inv + bv.x, acc.y * inv + bv.y,
                acc.z * inv + bv.z, acc.w * inv + bv.w};
    reinterpret_cast<float4*>(out)[node * 32 + lane] = o;
}

// ---------------------------------------------------------------------------
extern "C" void kernel_launch(void* const* d_in, const int* in_sizes, int n_in,
                              void* d_out, int out_size) {
    const float* x     = (const float*)d_in[0];
    const int*   ei    = (const int*)  d_in[1];
    const float* W     = (const float*)d_in[2];
    const float* bproj = (const float*)d_in[3];
    const float* att_s = (const float*)d_in[4];
    const float* att_d = (const float*)d_in[5];
    const float* bias  = (const float*)d_in[6];
    float* out = (float*)d_out;

    const int n = in_sizes[0] / 128;
    const int E = in_sizes[1] / 2;
    const int nb = (n + 1023) >> 10;

    static cudaStream_t s_csr = nullptr;
    static cudaEvent_t ev_fork = nullptr, ev_join = nullptr;
    if (!s_csr) {
        cudaStreamCreateWithFlags(&s_csr, cudaStreamNonBlocking);
        cudaEventCreateWithFlags(&ev_fork, cudaEventDisableTiming);
        cudaEventCreateWithFlags(&ev_join, cudaEventDisableTiming);
    }

    cudaEventRecord(ev_fork, 0);
    cudaStreamWaitEvent(s_csr, ev_fork, 0);
    zero_kernel<<<(n + 255) / 256, 256, 0, s_csr>>>(n);
    hist_kernel<<<(E + 255) / 256, 256, 0, s_csr>>>(ei, E);
    scan1_kernel<<<nb, 256, 0, s_csr>>>(n);
    scan3_kernel<<<nb, 256, 0, s_csr>>>(n, nb);
    fill_kernel<<<(E + 255) / 256, 256, 0, s_csr>>>(ei, E);
    cudaEventRecord(ev_join, s_csr);

    gemm_kernel<<<(n + 63) / 64, 256>>>(x, W, bproj, att_s, att_d, n);

    cudaStreamWaitEvent(0, ev_join, 0);
    gather_kernel<<<(n + 1) / 2, 64>>>(bias, out, n);
}